// round 1
// baseline (speedup 1.0000x reference)
#include <cuda_runtime.h>
#include <cuda_bf16.h>
#include <cstdint>

#define N_NODES 50000
#define N_EDGES 1600000
#define FEAT    48
#define NREL    8

// Scratch: h2[node][rel][feat] = 50000*8*48 floats = 76.8 MB (fits in L2 for the gather)
__device__ float g_h2[(size_t)N_NODES * NREL * FEAT];

// ---------- packed f32x2 helpers ----------
__device__ __forceinline__ unsigned long long pack2(float lo, float hi) {
    unsigned long long r;
    asm("mov.b64 %0, {%1, %2};" : "=l"(r) : "f"(lo), "f"(hi));
    return r;
}
__device__ __forceinline__ void unpack2(float& lo, float& hi, unsigned long long v) {
    asm("mov.b64 {%0, %1}, %2;" : "=f"(lo), "=f"(hi) : "l"(v));
}
__device__ __forceinline__ void fma2(unsigned long long& d, unsigned long long a, unsigned long long b) {
    asm("fma.rn.f32x2 %0, %1, %2, %0;" : "+l"(d) : "l"(a), "l"(b));
}

// ============================================================================
// Kernel A: h2[n,r,:] = relu(x[n] @ W1[r] + b1) @ W2[r]
// One thread per (node, rel). Weights in SMEM as packed float-pairs; inner
// products via fma.rn.f32x2 (2 fp32 FMAs per FMA-pipe issue slot).
// ============================================================================
__global__ void __launch_bounds__(256, 4) rgcn_precompute(
    const float* __restrict__ x,
    const float* __restrict__ W1,
    const float* __restrict__ W2,
    const float* __restrict__ b1)
{
    const int r = blockIdx.y;
    const int node = blockIdx.x * 256 + threadIdx.x;

    // 48x48 floats = 24 packed pairs per row, 1152 u64 per matrix
    __shared__ __align__(16) unsigned long long sW1[FEAT * 24];
    __shared__ __align__(16) unsigned long long sW2[FEAT * 24];
    __shared__ float sb1[FEAT];

    {
        const unsigned long long* g1 = (const unsigned long long*)(W1 + (size_t)r * FEAT * FEAT);
        const unsigned long long* g2 = (const unsigned long long*)(W2 + (size_t)r * FEAT * FEAT);
        for (int i = threadIdx.x; i < FEAT * 24; i += 256) {
            sW1[i] = g1[i];
            sW2[i] = g2[i];
        }
        if (threadIdx.x < FEAT) sb1[threadIdx.x] = b1[threadIdx.x];
    }
    __syncthreads();

    if (node >= N_NODES) return;

    // Load this node's feature row into registers (12 x LDG.128)
    float xv[FEAT];
    {
        const float4* xp = (const float4*)(x + (size_t)node * FEAT);
        #pragma unroll
        for (int q = 0; q < 12; q++) {
            float4 v = xp[q];
            xv[4 * q + 0] = v.x; xv[4 * q + 1] = v.y;
            xv[4 * q + 2] = v.z; xv[4 * q + 3] = v.w;
        }
    }

    // ---- Stage 1: h1 = relu(x @ W1 + b1) ----
    unsigned long long acc[24];
    #pragma unroll
    for (int q = 0; q < 24; q++) acc[q] = pack2(sb1[2 * q], sb1[2 * q + 1]);

    #pragma unroll 4
    for (int i = 0; i < FEAT; i++) {
        unsigned long long xi2 = pack2(xv[i], xv[i]);
        const ulonglong2* wrow = (const ulonglong2*)&sW1[i * 24];
        #pragma unroll
        for (int q = 0; q < 12; q++) {
            ulonglong2 w = wrow[q];        // LDS.128 broadcast
            fma2(acc[2 * q + 0], xi2, w.x);
            fma2(acc[2 * q + 1], xi2, w.y);
        }
    }

    float hs[FEAT];
    #pragma unroll
    for (int q = 0; q < 24; q++) {
        float lo, hi;
        unpack2(lo, hi, acc[q]);
        hs[2 * q + 0] = fmaxf(lo, 0.0f);
        hs[2 * q + 1] = fmaxf(hi, 0.0f);
    }

    // ---- Stage 2: h2 = h1 @ W2 ----
    #pragma unroll
    for (int q = 0; q < 24; q++) acc[q] = 0ull;

    #pragma unroll 4
    for (int i = 0; i < FEAT; i++) {
        unsigned long long xi2 = pack2(hs[i], hs[i]);
        const ulonglong2* wrow = (const ulonglong2*)&sW2[i * 24];
        #pragma unroll
        for (int q = 0; q < 12; q++) {
            ulonglong2 w = wrow[q];
            fma2(acc[2 * q + 0], xi2, w.x);
            fma2(acc[2 * q + 1], xi2, w.y);
        }
    }

    // Store: 12 x STG.128, layout h2[(node*NREL + r)*FEAT + j]
    ulonglong2* op = (ulonglong2*)(g_h2 + ((size_t)node * NREL + r) * FEAT);
    #pragma unroll
    for (int q = 0; q < 12; q++) {
        ulonglong2 v;
        v.x = acc[2 * q + 0];
        v.y = acc[2 * q + 1];
        op[q] = v;
    }
}

// ============================================================================
// Kernel B: per-edge gather + norm scale + vector reduce-add scatter.
// 4 threads per edge; each thread handles 12 consecutive floats (48B-aligned):
// 3 x LDG.128 gather + 3 x red.global.add.v4.f32.
// ============================================================================
__global__ void __launch_bounds__(256) rgcn_edge(
    const float* __restrict__ norm,
    const int*   __restrict__ src,
    const int*   __restrict__ dst,
    const int*   __restrict__ rel,
    float*       __restrict__ out)
{
    unsigned int t = blockIdx.x * 256u + threadIdx.x;   // E*4 threads exactly
    unsigned int e = t >> 2;
    unsigned int k = t & 3u;                            // which 12-float chunk

    int   s  = src[e];
    int   d  = dst[e];
    int   rt = rel[e];
    float nm = norm[e];

    const float4* p = (const float4*)(g_h2 + ((size_t)s * NREL + rt) * FEAT + k * 12u);
    float* o = out + (size_t)d * FEAT + k * 12u;

    #pragma unroll
    for (int q = 0; q < 3; q++) {
        float4 v = p[q];
        asm volatile(
            "red.global.add.v4.f32 [%0], {%1, %2, %3, %4};"
            :: "l"(o + q * 4),
               "f"(v.x * nm), "f"(v.y * nm), "f"(v.z * nm), "f"(v.w * nm)
            : "memory");
    }
}

// ============================================================================
// Kernel C: out = relu(out + bias2)
// ============================================================================
__global__ void __launch_bounds__(256) rgcn_bias_relu(
    float* __restrict__ out,
    const float* __restrict__ b2)
{
    unsigned int i = blockIdx.x * 256u + threadIdx.x;   // N_NODES*FEAT = 2.4M exactly
    unsigned int k = i - (i / FEAT) * FEAT;
    out[i] = fmaxf(out[i] + b2[k], 0.0f);
}

// ============================================================================
// Launch
// Inputs (metadata order): inputs, norm, weight1, weight2, bias1, bias2,
//                          src, dst, rel_type. Output: float [50000*48].
// ============================================================================
extern "C" void kernel_launch(void* const* d_in, const int* in_sizes, int n_in,
                              void* d_out, int out_size)
{
    const float* x    = (const float*)d_in[0];
    const float* norm = (const float*)d_in[1];
    const float* W1   = (const float*)d_in[2];
    const float* W2   = (const float*)d_in[3];
    const float* b1   = (const float*)d_in[4];
    const float* b2   = (const float*)d_in[5];
    const int*   src  = (const int*)d_in[6];
    const int*   dst  = (const int*)d_in[7];
    const int*   rel  = (const int*)d_in[8];
    float* out = (float*)d_out;

    // Zero the accumulation buffer (out is poisoned before timing)
    cudaMemsetAsync(d_out, 0, (size_t)out_size * sizeof(float));

    dim3 gridA((N_NODES + 255) / 256, NREL);
    rgcn_precompute<<<gridA, 256>>>(x, W1, W2, b1);

    rgcn_edge<<<(N_EDGES * 4) / 256, 256>>>(norm, src, dst, rel, out);

    rgcn_bias_relu<<<(N_NODES * FEAT) / 256, 256>>>(out, b2);
}

// round 3
// speedup vs baseline: 1.5610x; 1.5610x over previous
#include <cuda_runtime.h>
#include <cuda_bf16.h>
#include <cstdint>

#define N_NODES 50000
#define N_EDGES 1600000
#define FEAT    48
#define NREL    8
#define TILE    256
#define XSTRIDE 260   // padded row stride (floats), multiple of 4, low-conflict

// Scratch: h2[rel][node][feat] = 8*50000*48 floats = 76.8 MB (rel-major => block-contiguous stores)
__device__ float g_h2[(size_t)NREL * N_NODES * FEAT];

// ---------- packed f32x2 helpers ----------
__device__ __forceinline__ unsigned long long dup2(float v) {
    unsigned long long r;
    asm("mov.b64 %0, {%1, %1};" : "=l"(r) : "f"(v));
    return r;
}
__device__ __forceinline__ unsigned long long pack2(float lo, float hi) {
    unsigned long long r;
    asm("mov.b64 %0, {%1, %2};" : "=l"(r) : "f"(lo), "f"(hi));
    return r;
}
__device__ __forceinline__ void unpack2(float& lo, float& hi, unsigned long long v) {
    asm("mov.b64 {%0, %1}, %2;" : "=f"(lo), "=f"(hi) : "l"(v));
}
__device__ __forceinline__ void fma2(unsigned long long& d, unsigned long long a, unsigned long long b) {
    asm("fma.rn.f32x2 %0, %1, %2, %0;" : "+l"(d) : "l"(a), "l"(b));
}

// Dynamic smem layout (bytes):
//   [0, 12544*4)                  : sX / sH1 / sOut  (reused, stage-synced)
//   [50176, +2304*8)              : sW1dup  (48x48 u64, each (w,w))
//   [+2304*8)                     : sW2dup
//   [+48*8)                       : sb1dup
#define SMEM_F32   12544
#define SMEM_BYTES (SMEM_F32 * 4 + 2 * 2304 * 8 + 48 * 8)

// ============================================================================
// Kernel A: h2[r][n][:] = relu(x[n] @ W1[r] + b1) @ W2[r]
// Block: 256 threads, 256-node tile, one relation.
// Thread tile: 8 nodes x 6 outs = 24 f32x2 accumulators.
// Lane map: osub = lane>>2 (out group of 6), nsub = lane&3; warp owns 32 nodes.
// ============================================================================
__global__ void __launch_bounds__(256, 2) rgcn_precompute(
    const float* __restrict__ x,
    const float* __restrict__ W1,
    const float* __restrict__ W2,
    const float* __restrict__ b1)
{
    extern __shared__ __align__(16) unsigned char smem_raw[];
    float* sX = (float*)smem_raw;
    unsigned long long* sW1d = (unsigned long long*)(smem_raw + SMEM_F32 * 4);
    unsigned long long* sW2d = sW1d + 2304;
    unsigned long long* sb1d = sW2d + 2304;

    const int r        = blockIdx.y;
    const int tileBase = blockIdx.x * TILE;
    const int tid      = threadIdx.x;

    // ---- stage weights (duplicated as f32x2) + bias ----
    {
        const float* w1 = W1 + (size_t)r * FEAT * FEAT;
        const float* w2 = W2 + (size_t)r * FEAT * FEAT;
        #pragma unroll
        for (int m = tid; m < FEAT * FEAT; m += 256) {
            sW1d[m] = dup2(w1[m]);
            sW2d[m] = dup2(w2[m]);
        }
        if (tid < FEAT) sb1d[tid] = dup2(b1[tid]);
    }

    // ---- stage X tile transposed: sX[feat][node] ----
    {
        const float4* xg = (const float4*)x;
        const int base4 = tileBase * 12;
        #pragma unroll
        for (int it = 0; it < 12; it++) {
            int idx  = it * 256 + tid;          // 0..3071
            int node = idx / 12;
            int c    = idx % 12;
            float4 v = make_float4(0.f, 0.f, 0.f, 0.f);
            if (tileBase + node < N_NODES) v = xg[base4 + idx];
            sX[(c * 4 + 0) * XSTRIDE + node] = v.x;
            sX[(c * 4 + 1) * XSTRIDE + node] = v.y;
            sX[(c * 4 + 2) * XSTRIDE + node] = v.z;
            sX[(c * 4 + 3) * XSTRIDE + node] = v.w;
        }
    }
    __syncthreads();

    const int lane = tid & 31;
    const int warp = tid >> 5;
    const int osub = lane >> 2;          // out group: outs osub*6 .. +5
    const int nsub = lane & 3;
    const int nA   = warp * 32 + 4 * nsub;   // nodes nA..nA+3
    const int nB   = nA + 16;                // nodes nB..nB+3

    unsigned long long acc[4][6];

    // ================= Stage 1: h1 = relu(x @ W1 + b1) =================
    #pragma unroll
    for (int p = 0; p < 4; p++)
        #pragma unroll
        for (int j = 0; j < 6; j++)
            acc[p][j] = sb1d[osub * 6 + j];

    #pragma unroll 4
    for (int k = 0; k < FEAT; k++) {
        const float* xrow = sX + k * XSTRIDE;
        ulonglong2 xa = *(const ulonglong2*)(xrow + nA);   // node pairs p0,p1
        ulonglong2 xb = *(const ulonglong2*)(xrow + nB);   // node pairs p2,p3
        const unsigned long long* wr = sW1d + k * FEAT + osub * 6;
        #pragma unroll
        for (int j = 0; j < 6; j++) {
            unsigned long long w = wr[j];
            fma2(acc[0][j], xa.x, w);
            fma2(acc[1][j], xa.y, w);
            fma2(acc[2][j], xb.x, w);
            fma2(acc[3][j], xb.y, w);
        }
    }

    // relu, write h1 transposed into the same buffer: sH1[out][node]
    __syncthreads();
    #pragma unroll
    for (int p = 0; p < 4; p++) {
        int n = (p < 2) ? (nA + 2 * p) : (nB + 2 * (p - 2));
        #pragma unroll
        for (int j = 0; j < 6; j++) {
            float lo, hi;
            unpack2(lo, hi, acc[p][j]);
            lo = fmaxf(lo, 0.f);
            hi = fmaxf(hi, 0.f);
            *(unsigned long long*)(sX + (osub * 6 + j) * XSTRIDE + n) = pack2(lo, hi);
        }
    }
    __syncthreads();

    // ================= Stage 2: h2 = h1 @ W2 =================
    #pragma unroll
    for (int p = 0; p < 4; p++)
        #pragma unroll
        for (int j = 0; j < 6; j++)
            acc[p][j] = 0ull;

    #pragma unroll 4
    for (int k = 0; k < FEAT; k++) {
        const float* xrow = sX + k * XSTRIDE;
        ulonglong2 xa = *(const ulonglong2*)(xrow + nA);
        ulonglong2 xb = *(const ulonglong2*)(xrow + nB);
        const unsigned long long* wr = sW2d + k * FEAT + osub * 6;
        #pragma unroll
        for (int j = 0; j < 6; j++) {
            unsigned long long w = wr[j];
            fma2(acc[0][j], xa.x, w);
            fma2(acc[1][j], xa.y, w);
            fma2(acc[2][j], xb.x, w);
            fma2(acc[3][j], xb.y, w);
        }
    }

    // ---- transpose in smem -> coalesced contiguous store ----
    __syncthreads();
    {
        float* sOut = sX;   // reuse, now as [node][out] with stride 49
        #pragma unroll
        for (int p = 0; p < 4; p++) {
            int n = (p < 2) ? (nA + 2 * p) : (nB + 2 * (p - 2));
            #pragma unroll
            for (int j = 0; j < 6; j++) {
                float lo, hi;
                unpack2(lo, hi, acc[p][j]);
                int o = osub * 6 + j;
                sOut[n * 49 + o]       = lo;
                sOut[(n + 1) * 49 + o] = hi;
            }
        }
    }
    __syncthreads();
    {
        const float* sOut = sX;
        float* dst = g_h2 + ((size_t)r * N_NODES + tileBase) * FEAT;
        int valid = N_NODES - tileBase;
        if (valid > TILE) valid = TILE;
        int total = valid * FEAT;
        for (int i = tid; i < total; i += 256) {
            int node = i / FEAT;
            int o    = i - node * FEAT;
            dst[i] = sOut[node * 49 + o];
        }
    }
}

// ============================================================================
// Kernel B: per-edge gather + norm scale + vector reduce-add scatter.
// 4 threads per edge; each handles 12 consecutive floats.
// ============================================================================
__global__ void __launch_bounds__(256) rgcn_edge(
    const float* __restrict__ norm,
    const int*   __restrict__ src,
    const int*   __restrict__ dst,
    const int*   __restrict__ rel,
    float*       __restrict__ out)
{
    unsigned int t = blockIdx.x * 256u + threadIdx.x;   // E*4 threads exactly
    unsigned int e = t >> 2;
    unsigned int k = t & 3u;

    int   s  = src[e];
    int   d  = dst[e];
    int   rt = rel[e];
    float nm = norm[e];

    const float4* p = (const float4*)(g_h2 + ((size_t)rt * N_NODES + s) * FEAT + k * 12u);
    float* o = out + (size_t)d * FEAT + k * 12u;

    #pragma unroll
    for (int q = 0; q < 3; q++) {
        float4 v = p[q];
        asm volatile(
            "red.global.add.v4.f32 [%0], {%1, %2, %3, %4};"
            :: "l"(o + q * 4),
               "f"(v.x * nm), "f"(v.y * nm), "f"(v.z * nm), "f"(v.w * nm)
            : "memory");
    }
}

// ============================================================================
// Kernel C: out = relu(out + bias2)
// ============================================================================
__global__ void __launch_bounds__(256) rgcn_bias_relu(
    float* __restrict__ out,
    const float* __restrict__ b2)
{
    unsigned int i = blockIdx.x * 256u + threadIdx.x;   // N_NODES*FEAT exactly
    unsigned int k = i - (i / FEAT) * FEAT;
    out[i] = fmaxf(out[i] + b2[k], 0.0f);
}

// ============================================================================
// Launch
// ============================================================================
extern "C" void kernel_launch(void* const* d_in, const int* in_sizes, int n_in,
                              void* d_out, int out_size)
{
    const float* x    = (const float*)d_in[0];
    const float* norm = (const float*)d_in[1];
    const float* W1   = (const float*)d_in[2];
    const float* W2   = (const float*)d_in[3];
    const float* b1   = (const float*)d_in[4];
    const float* b2   = (const float*)d_in[5];
    const int*   src  = (const int*)d_in[6];
    const int*   dst  = (const int*)d_in[7];
    const int*   rel  = (const int*)d_in[8];
    float* out = (float*)d_out;

    cudaFuncSetAttribute(rgcn_precompute,
                         cudaFuncAttributeMaxDynamicSharedMemorySize, SMEM_BYTES);

    cudaMemsetAsync(d_out, 0, (size_t)out_size * sizeof(float));

    dim3 gridA((N_NODES + TILE - 1) / TILE, NREL);
    rgcn_precompute<<<gridA, 256, SMEM_BYTES>>>(x, W1, W2, b1);

    rgcn_edge<<<(N_EDGES * 4) / 256, 256>>>(norm, src, dst, rel, out);

    rgcn_bias_relu<<<(N_NODES * FEAT) / 256, 256>>>(out, b2);
}